// round 12
// baseline (speedup 1.0000x reference)
#include <cuda_runtime.h>

#define N_NODES  100000
#define F_IN     256
#define F_HID    64
#define F_OUT    40
#define EDGE_MAX 1700000

// Scratch (static device globals — no allocation allowed)
__device__ float  g_dis[N_NODES];             // rsqrt(weighted deg + 1)
__device__ float  g_deg[N_NODES];             // weighted degree accumulator
__device__ int    g_cnt[N_NODES];             // edges per destination
__device__ int    g_excl[N_NODES];            // local exclusive scan
__device__ int    g_bsum[512];                // per-block totals
__device__ int    g_rowptr[N_NODES];          // CSR row starts
__device__ int    g_fill[N_NODES];            // fill cursors
__device__ float2 g_edge[EDGE_MAX];           // (src as int bits, nrm)
__device__ float4 g_wpack[8192];              // W1 tf32 hi/lo in mma-frag order
__device__ float  g_h1[N_NODES * F_HID];      // x @ W1
__device__ float  g_agg1[N_NODES * F_HID];    // relu(agg + self + b1)
__device__ float  g_h2[N_NODES * F_OUT];      // relu_out @ W2

// ---------------------------------------------------------------------------
// Packed f32x2 helpers (FFMA2 path, used by gemm2)
// ---------------------------------------------------------------------------
__device__ __forceinline__ unsigned long long f2pack(float lo, float hi) {
    unsigned long long r;
    asm("mov.b64 %0, {%1, %2};" : "=l"(r) : "f"(lo), "f"(hi));
    return r;
}
__device__ __forceinline__ void f2unpack(unsigned long long v, float& lo, float& hi) {
    asm("mov.b64 {%0, %1}, %2;" : "=f"(lo), "=f"(hi) : "l"(v));
}
__device__ __forceinline__ void fma2(unsigned long long& d,
                                     unsigned long long a, unsigned long long b) {
    asm("fma.rn.f32x2 %0, %1, %2, %0;" : "+l"(d) : "l"(a), "l"(b));
}
__device__ __forceinline__ void lds_v2u64(unsigned long long& a, unsigned long long& b,
                                          const void* p) {
    unsigned s = (unsigned)__cvta_generic_to_shared(p);
    asm volatile("ld.shared.v2.u64 {%0, %1}, [%2];" : "=l"(a), "=l"(b) : "r"(s));
}

// ---------------------------------------------------------------------------
// tf32 helpers
// ---------------------------------------------------------------------------
__device__ __forceinline__ unsigned to_tf32(float f) {
    unsigned r;
    asm("cvt.rna.tf32.f32 %0, %1;" : "=r"(r) : "f"(f));
    return r;
}
__device__ __forceinline__ void mma_tf32(float c[4], const unsigned a[4],
                                         const unsigned b[2]) {
    asm volatile(
        "mma.sync.aligned.m16n8k8.row.col.f32.tf32.tf32.f32 "
        "{%0,%1,%2,%3}, {%4,%5,%6,%7}, {%8,%9}, {%0,%1,%2,%3};\n"
        : "+f"(c[0]), "+f"(c[1]), "+f"(c[2]), "+f"(c[3])
        : "r"(a[0]), "r"(a[1]), "r"(a[2]), "r"(a[3]), "r"(b[0]), "r"(b[1]));
}

// ---------------------------------------------------------------------------
// CSR build
// ---------------------------------------------------------------------------
__global__ void k_zero_cd(int n) {
    int i = blockIdx.x * blockDim.x + threadIdx.x;
    if (i < n) { g_cnt[i] = 0; g_deg[i] = 0.0f; }
}

__global__ void k_count(const int* __restrict__ ei,
                        const float* __restrict__ ew, int E) {
    int e = blockIdx.x * blockDim.x + threadIdx.x;
    if (e < E) {
        int c = ei[E + e];
        atomicAdd(&g_cnt[c], 1);
        atomicAdd(&g_deg[c], ew[e]);
    }
}

// Pack W1 into tf32 hi/lo mma-fragment order:
// g_wpack[((kc*4+ks)*8+nb)*32+lane] = (hi(k,n), hi(k+4,n), lo(k,n), lo(k+4,n))
// where k = kc*32+ks*8+(lane&3), n = nb*8+(lane>>2).
__global__ void k_packW1(const float* __restrict__ W1) {
    int idx = blockIdx.x * blockDim.x + threadIdx.x;
    if (idx >= 8192) return;
    int lane = idx & 31;
    int nb   = (idx >> 5) & 7;
    int ks   = (idx >> 8) & 3;
    int kc   = idx >> 10;
    int g    = lane >> 2;
    int tg   = lane & 3;
    int k = kc * 32 + ks * 8 + tg;
    int n = nb * 8 + g;
    float w0 = W1[k * F_HID + n];
    float w1 = W1[(k + 4) * F_HID + n];
    float h0 = __uint_as_float(to_tf32(w0));
    float h1 = __uint_as_float(to_tf32(w1));
    float l0 = __uint_as_float(to_tf32(w0 - h0));
    float l1 = __uint_as_float(to_tf32(w1 - h1));
    g_wpack[idx] = make_float4(h0, h1, l0, l1);
}

// exclusive scan, stage 1: 256-element chunks
__global__ void k_scan_local(int n) {
    __shared__ int s[256];
    int tid = threadIdx.x;
    int gid = blockIdx.x * 256 + tid;
    int v = (gid < n) ? g_cnt[gid] : 0;
    s[tid] = v;
    #pragma unroll
    for (int off = 1; off < 256; off <<= 1) {
        __syncthreads();
        int t = (tid >= off) ? s[tid - off] : 0;
        __syncthreads();
        s[tid] += t;
    }
    __syncthreads();
    if (gid < n) g_excl[gid] = s[tid] - v;
    if (tid == 255) g_bsum[blockIdx.x] = s[255];
}

// stage 2 (fused): each block reduces bsum[0..bid) inline; init rowptr/fill/dis
__global__ void k_scan_add(int n) {
    __shared__ int red[256];
    int tid = threadIdx.x;
    int bid = blockIdx.x;
    int s = 0;
    for (int j = tid; j < bid; j += 256) s += g_bsum[j];
    red[tid] = s;
    __syncthreads();
    #pragma unroll
    for (int off = 128; off > 0; off >>= 1) {
        if (tid < off) red[tid] += red[tid + off];
        __syncthreads();
    }
    int base = red[0];
    int i = bid * 256 + tid;
    if (i < n) {
        int v = g_excl[i] + base;
        g_rowptr[i] = v;
        g_fill[i]   = v;
        g_dis[i]    = rsqrtf(g_deg[i] + 1.0f);   // +1 = self-loop weight
    }
}

// scatter edges into CSR; precompute nrm = dis[src]*w*dis[dst]
__global__ void k_fill(const int* __restrict__ ei,
                       const float* __restrict__ ew, int E) {
    int e = blockIdx.x * blockDim.x + threadIdx.x;
    if (e >= E) return;
    int r = ei[e];
    int c = ei[E + e];
    float nrm = g_dis[r] * ew[e] * g_dis[c];
    int pos = atomicAdd(&g_fill[c], 1);
    g_edge[pos] = make_float2(__int_as_float(r), nrm);
}

// ---------------------------------------------------------------------------
// GEMM1 (tensor): g_h1[N,64] = x[N,256] @ W1[256,64] via 3xTF32 mma.sync.
// 256 thr = 8 warps; tile 128 rows x 64 cols; warp w -> rows w*16..+15.
// A hi/lo pre-split at staging (xs2 float2, pad 36: conflict-free LDS.64).
// B fragments read directly from g_wpack (one LDG.128 per nb; L1-resident,
// identical addresses across warps).
// Inner loop per k8-step: 4 LDS.64 + 8 LDG.128 + 12 mma.
// ---------------------------------------------------------------------------
#define G1_ROWS 128

__global__ void k_gemm1(const float* __restrict__ x) {
    __shared__ float2 xs2[G1_ROWS][36];   // (hi, lo), 36 KB

    int t    = threadIdx.x;
    int lane = t & 31;
    int w    = t >> 5;            // warp 0..7
    int g    = lane >> 2;         // group 0..7
    int tg   = lane & 3;          // 0..3
    int row0 = blockIdx.x * G1_ROWS;
    int rb   = w * 16;

    float c[8][4];
    #pragma unroll
    for (int nb = 0; nb < 8; nb++)
        #pragma unroll
        for (int i = 0; i < 4; i++) c[nb][i] = 0.0f;

    for (int kc = 0; kc < 8; kc++) {            // k-chunks of 32
        // stage x tile: 128 rows x 32 k, split hi/lo at load
        #pragma unroll
        for (int j = 0; j < 4; j++) {
            int idx = t + j * 256;
            int r   = idx >> 3;
            int f4  = idx & 7;
            int gr  = row0 + r;
            if (gr >= N_NODES) gr = N_NODES - 1;   // clamped (result discarded)
            float4 v = *(const float4*)(x + (size_t)gr * F_IN + kc * 32 + f4 * 4);
            float h0 = __uint_as_float(to_tf32(v.x));
            float h1 = __uint_as_float(to_tf32(v.y));
            float h2 = __uint_as_float(to_tf32(v.z));
            float h3 = __uint_as_float(to_tf32(v.w));
            float l0 = __uint_as_float(to_tf32(v.x - h0));
            float l1 = __uint_as_float(to_tf32(v.y - h1));
            float l2 = __uint_as_float(to_tf32(v.z - h2));
            float l3 = __uint_as_float(to_tf32(v.w - h3));
            *(float4*)&xs2[r][f4 * 4]     = make_float4(h0, l0, h1, l1);
            *(float4*)&xs2[r][f4 * 4 + 2] = make_float4(h2, l2, h3, l3);
        }
        __syncthreads();

        const float4* wp = g_wpack + kc * 1024;
        #pragma unroll
        for (int ks = 0; ks < 4; ks++) {        // 4 k8-steps per chunk
            int k0 = ks * 8;
            float2 p0 = xs2[rb + g][k0 + tg];
            float2 p1 = xs2[rb + g + 8][k0 + tg];
            float2 p2 = xs2[rb + g][k0 + tg + 4];
            float2 p3 = xs2[rb + g + 8][k0 + tg + 4];
            unsigned ahi[4] = {__float_as_uint(p0.x), __float_as_uint(p1.x),
                               __float_as_uint(p2.x), __float_as_uint(p3.x)};
            unsigned alo[4] = {__float_as_uint(p0.y), __float_as_uint(p1.y),
                               __float_as_uint(p2.y), __float_as_uint(p3.y)};

            #pragma unroll
            for (int nb = 0; nb < 8; nb++) {
                float4 bv = __ldg(&wp[(ks * 8 + nb) * 32 + lane]);
                unsigned bh[2] = {__float_as_uint(bv.x), __float_as_uint(bv.y)};
                unsigned bl[2] = {__float_as_uint(bv.z), __float_as_uint(bv.w)};
                mma_tf32(c[nb], ahi, bh);
                mma_tf32(c[nb], alo, bh);
                mma_tf32(c[nb], ahi, bl);
            }
        }
        __syncthreads();
    }

    int gr0 = row0 + rb + g;
    int gr1 = gr0 + 8;
    #pragma unroll
    for (int nb = 0; nb < 8; nb++) {
        int col = nb * 8 + 2 * tg;
        if (gr0 < N_NODES)
            *(float2*)(g_h1 + (size_t)gr0 * F_HID + col) =
                make_float2(c[nb][0], c[nb][1]);
        if (gr1 < N_NODES)
            *(float2*)(g_h1 + (size_t)gr1 * F_HID + col) =
                make_float2(c[nb][2], c[nb][3]);
    }
}

// ---------------------------------------------------------------------------
// Layer-1 CSR aggregation: 16 threads per node, gather-only, no atomics.
// Fuses self-loop + bias + relu.
// ---------------------------------------------------------------------------
__global__ void k_agg1_csr(const float* __restrict__ b1) {
    int idx  = blockIdx.x * blockDim.x + threadIdx.x;
    int node = idx >> 4;
    int c    = idx & 15;
    if (node >= N_NODES) return;
    int beg = g_rowptr[node];
    int cnt = g_cnt[node];
    float di = g_dis[node];

    float4 acc = make_float4(0.f, 0.f, 0.f, 0.f);
    int j = 0;
    for (; j + 1 < cnt; j += 2) {
        float2 e0 = g_edge[beg + j];
        float2 e1 = g_edge[beg + j + 1];
        int s0 = __float_as_int(e0.x);
        int s1 = __float_as_int(e1.x);
        float4 v0 = *(const float4*)(g_h1 + (size_t)s0 * F_HID + c * 4);
        float4 v1 = *(const float4*)(g_h1 + (size_t)s1 * F_HID + c * 4);
        acc.x += e0.y * v0.x + e1.y * v1.x;
        acc.y += e0.y * v0.y + e1.y * v1.y;
        acc.z += e0.y * v0.z + e1.y * v1.z;
        acc.w += e0.y * v0.w + e1.y * v1.w;
    }
    if (j < cnt) {
        float2 e0 = g_edge[beg + j];
        int s0 = __float_as_int(e0.x);
        float4 v0 = *(const float4*)(g_h1 + (size_t)s0 * F_HID + c * 4);
        acc.x += e0.y * v0.x;
        acc.y += e0.y * v0.y;
        acc.z += e0.y * v0.z;
        acc.w += e0.y * v0.w;
    }

    float s2 = di * di;
    float4 h = *(const float4*)(g_h1 + (size_t)node * F_HID + c * 4);
    float4 b = ((const float4*)b1)[c];
    float4 o;
    o.x = fmaxf(acc.x + s2 * h.x + b.x, 0.0f);
    o.y = fmaxf(acc.y + s2 * h.y + b.y, 0.0f);
    o.z = fmaxf(acc.z + s2 * h.z + b.z, 0.0f);
    o.w = fmaxf(acc.w + s2 * h.w + b.w, 0.0f);
    *(float4*)(g_agg1 + (size_t)node * F_HID + c * 4) = o;
}

// ---------------------------------------------------------------------------
// GEMM2: g_h2[N,40] = g_agg1[N,64] @ W2[64,40]   (FFMA2, R6 config)
// ---------------------------------------------------------------------------
#define G2_ROWS 128

__global__ void k_gemm2(const float* __restrict__ W2) {
    __shared__ float rs[F_HID][G2_ROWS];   // 32 KB, k-major
    __shared__ float ws2[F_HID][F_OUT];    // 10 KB

    int t    = threadIdx.x;
    int row0 = blockIdx.x * G2_ROWS;
    int tx   = t & 7;         // cols tx*5 .. +4
    int ty   = t >> 3;        // rows ty*4 .. +3

    #pragma unroll
    for (int j = 0; j < 3; j++) {
        int i = t + j * 256;
        if (i < 640) ((float4*)ws2)[i] = ((const float4*)W2)[i];
    }
    #pragma unroll
    for (int j = 0; j < 8; j++) {
        int idx = t + j * 256;
        int r   = idx & 127;
        int kq  = idx >> 7;
        int gr  = row0 + r;
        if (gr >= N_NODES) gr = N_NODES - 1;
        float4 v = *(const float4*)(g_agg1 + (size_t)gr * F_HID + kq * 4);
        rs[kq * 4 + 0][r] = v.x;
        rs[kq * 4 + 1][r] = v.y;
        rs[kq * 4 + 2][r] = v.z;
        rs[kq * 4 + 3][r] = v.w;
    }
    __syncthreads();

    unsigned long long acc2[2][5];
    #pragma unroll
    for (int p = 0; p < 2; p++)
        #pragma unroll
        for (int j = 0; j < 5; j++) acc2[p][j] = f2pack(0.0f, 0.0f);

    #pragma unroll
    for (int kk = 0; kk < F_HID; kk++) {
        unsigned long long ap0, ap1;
        lds_v2u64(ap0, ap1, &rs[kk][ty * 4]);
        const float* wrow = &ws2[kk][tx * 5];
        #pragma unroll
        for (int j = 0; j < 5; j++) {
            float bj = wrow[j];
            unsigned long long bd = f2pack(bj, bj);
            fma2(acc2[0][j], ap0, bd);
            fma2(acc2[1][j], ap1, bd);
        }
    }

    #pragma unroll
    for (int p = 0; p < 2; p++) {
        float lo[5], hi[5];
        #pragma unroll
        for (int j = 0; j < 5; j++) f2unpack(acc2[p][j], lo[j], hi[j]);
        int gr0 = row0 + ty * 4 + 2 * p;
        if (gr0 < N_NODES) {
            float* o = g_h2 + (size_t)gr0 * F_OUT + tx * 5;
            #pragma unroll
            for (int j = 0; j < 5; j++) o[j] = lo[j];
        }
        if (gr0 + 1 < N_NODES) {
            float* o = g_h2 + (size_t)(gr0 + 1) * F_OUT + tx * 5;
            #pragma unroll
            for (int j = 0; j < 5; j++) o[j] = hi[j];
        }
    }
}

// ---------------------------------------------------------------------------
// Layer-2 CSR aggregation: 10 threads/node (all active), fuses b2 + self-loop.
// ---------------------------------------------------------------------------
__global__ void k_agg2_csr(const float* __restrict__ b2,
                           float* __restrict__ out) {
    int idx  = blockIdx.x * blockDim.x + threadIdx.x;
    int node = idx / 10;
    int c    = idx - node * 10;
    if (node >= N_NODES) return;
    int beg = g_rowptr[node];
    int cnt = g_cnt[node];
    float di = g_dis[node];

    float4 acc = make_float4(0.f, 0.f, 0.f, 0.f);
    int j = 0;
    for (; j + 1 < cnt; j += 2) {
        float2 e0 = g_edge[beg + j];
        float2 e1 = g_edge[beg + j + 1];
        int s0 = __float_as_int(e0.x);
        int s1 = __float_as_int(e1.x);
        float4 v0 = *(const float4*)(g_h2 + (size_t)s0 * F_OUT + c * 4);
        float4 v1 = *(const float4*)(g_h2 + (size_t)s1 * F_OUT + c * 4);
        acc.x += e0.y * v0.x + e1.y * v1.x;
        acc.y += e0.y * v0.y + e1.y * v1.y;
        acc.z += e0.y * v0.z + e1.y * v1.z;
        acc.w += e0.y * v0.w + e1.y * v1.w;
    }
    if (j < cnt) {
        float2 e0 = g_edge[beg + j];
        int s0 = __float_as_int(e0.x);
        float4 v0 = *(const float4*)(g_h2 + (size_t)s0 * F_OUT + c * 4);
        acc.x += e0.y * v0.x;
        acc.y += e0.y * v0.y;
        acc.z += e0.y * v0.z;
        acc.w += e0.y * v0.w;
    }

    float s2 = di * di;
    float4 h = *(const float4*)(g_h2 + (size_t)node * F_OUT + c * 4);
    float4 b = ((const float4*)b2)[c];
    float4 o;
    o.x = acc.x + s2 * h.x + b.x;
    o.y = acc.y + s2 * h.y + b.y;
    o.z = acc.z + s2 * h.z + b.z;
    o.w = acc.w + s2 * h.w + b.w;
    *(float4*)(out + (size_t)node * F_OUT + c * 4) = o;
}

// ---------------------------------------------------------------------------
extern "C" void kernel_launch(void* const* d_in, const int* in_sizes, int n_in,
                              void* d_out, int out_size) {
    const float* x  = (const float*)d_in[0];
    const int*   ei = (const int*)d_in[1];
    const float* ew = (const float*)d_in[2];
    const float* W1 = (const float*)d_in[3];
    const float* b1 = (const float*)d_in[4];
    const float* W2 = (const float*)d_in[5];
    const float* b2 = (const float*)d_in[6];
    float* out = (float*)d_out;

    int N = in_sizes[0] / F_IN;     // 100000
    int E = in_sizes[2];            // 1600000
    int nblk = (N + 255) / 256;     // 391

    // CSR build + normalization + W pack
    k_zero_cd<<<nblk, 256>>>(N);
    k_packW1<<<32, 256>>>(W1);
    k_count<<<(E + 255) / 256, 256>>>(ei, ew, E);
    k_scan_local<<<nblk, 256>>>(N);
    k_scan_add<<<nblk, 256>>>(N);      // fused bsum-reduce + rowptr + dis
    k_fill<<<(E + 255) / 256, 256>>>(ei, ew, E);

    // layer 1
    k_gemm1<<<(N + G1_ROWS - 1) / G1_ROWS, 256>>>(x);
    {
        long long items = (long long)N * 16;
        k_agg1_csr<<<(int)((items + 255) / 256), 256>>>(b1);
    }

    // layer 2
    k_gemm2<<<(N + G2_ROWS - 1) / G2_ROWS, 256>>>(W2);
    {
        long long items = (long long)N * 10;
        k_agg2_csr<<<(int)((items + 255) / 256), 256>>>(b2, out);
    }
}

// round 13
// speedup vs baseline: 1.1043x; 1.1043x over previous
#include <cuda_runtime.h>

#define N_NODES  100000
#define F_IN     256
#define F_HID    64
#define F_OUT    40
#define EDGE_MAX 1700000

// Scratch (static device globals — no allocation allowed)
__device__ float  g_dis[N_NODES];             // rsqrt(weighted deg + 1)
__device__ float  g_deg[N_NODES];             // weighted degree accumulator
__device__ int    g_cnt[N_NODES];             // edges per destination
__device__ int    g_excl[N_NODES];            // local exclusive scan
__device__ int    g_bsum[512];                // per-block totals
__device__ int    g_rowptr[N_NODES];          // CSR row starts
__device__ int    g_fill[N_NODES];            // fill cursors
__device__ float2 g_edge[EDGE_MAX];           // (src as int bits, nrm)
__device__ float4 g_wpack[8192];              // W1 tf32 hi/lo in mma-frag order
__device__ float  g_h1[N_NODES * F_HID];      // x @ W1
__device__ float  g_agg1[N_NODES * F_HID];    // relu(agg + self + b1)
__device__ float  g_h2[N_NODES * F_OUT];      // relu_out @ W2

// ---------------------------------------------------------------------------
// Packed f32x2 helpers (FFMA2 path, used by gemm2)
// ---------------------------------------------------------------------------
__device__ __forceinline__ unsigned long long f2pack(float lo, float hi) {
    unsigned long long r;
    asm("mov.b64 %0, {%1, %2};" : "=l"(r) : "f"(lo), "f"(hi));
    return r;
}
__device__ __forceinline__ void f2unpack(unsigned long long v, float& lo, float& hi) {
    asm("mov.b64 {%0, %1}, %2;" : "=f"(lo), "=f"(hi) : "l"(v));
}
__device__ __forceinline__ void fma2(unsigned long long& d,
                                     unsigned long long a, unsigned long long b) {
    asm("fma.rn.f32x2 %0, %1, %2, %0;" : "+l"(d) : "l"(a), "l"(b));
}
__device__ __forceinline__ void lds_v2u64(unsigned long long& a, unsigned long long& b,
                                          const void* p) {
    unsigned s = (unsigned)__cvta_generic_to_shared(p);
    asm volatile("ld.shared.v2.u64 {%0, %1}, [%2];" : "=l"(a), "=l"(b) : "r"(s));
}

// ---------------------------------------------------------------------------
// tf32 helpers
// ---------------------------------------------------------------------------
__device__ __forceinline__ unsigned to_tf32(float f) {
    unsigned r;
    asm("cvt.rna.tf32.f32 %0, %1;" : "=r"(r) : "f"(f));
    return r;
}
__device__ __forceinline__ void mma_tf32(float c[4], const unsigned a[4],
                                         const unsigned b[2]) {
    asm volatile(
        "mma.sync.aligned.m16n8k8.row.col.f32.tf32.tf32.f32 "
        "{%0,%1,%2,%3}, {%4,%5,%6,%7}, {%8,%9}, {%0,%1,%2,%3};\n"
        : "+f"(c[0]), "+f"(c[1]), "+f"(c[2]), "+f"(c[3])
        : "r"(a[0]), "r"(a[1]), "r"(a[2]), "r"(a[3]), "r"(b[0]), "r"(b[1]));
}

// ---------------------------------------------------------------------------
// CSR build
// ---------------------------------------------------------------------------
__global__ void k_zero_cd(int n) {
    int i = blockIdx.x * blockDim.x + threadIdx.x;
    if (i < n) { g_cnt[i] = 0; g_deg[i] = 0.0f; }
}

__global__ void k_count(const int* __restrict__ ei,
                        const float* __restrict__ ew, int E) {
    int e = blockIdx.x * blockDim.x + threadIdx.x;
    if (e < E) {
        int c = ei[E + e];
        atomicAdd(&g_cnt[c], 1);
        atomicAdd(&g_deg[c], ew[e]);
    }
}

// Pack W1 into tf32 hi/lo mma-fragment order:
// g_wpack[((kc*4+ks)*8+nb)*32+lane] = (hi(k,n), hi(k+4,n), lo(k,n), lo(k+4,n))
// where k = kc*32+ks*8+(lane&3), n = nb*8+(lane>>2).
__global__ void k_packW1(const float* __restrict__ W1) {
    int idx = blockIdx.x * blockDim.x + threadIdx.x;
    if (idx >= 8192) return;
    int lane = idx & 31;
    int nb   = (idx >> 5) & 7;
    int ks   = (idx >> 8) & 3;
    int kc   = idx >> 10;
    int g    = lane >> 2;
    int tg   = lane & 3;
    int k = kc * 32 + ks * 8 + tg;
    int n = nb * 8 + g;
    float w0 = W1[k * F_HID + n];
    float w1 = W1[(k + 4) * F_HID + n];
    float h0 = __uint_as_float(to_tf32(w0));
    float h1 = __uint_as_float(to_tf32(w1));
    float l0 = __uint_as_float(to_tf32(w0 - h0));
    float l1 = __uint_as_float(to_tf32(w1 - h1));
    g_wpack[idx] = make_float4(h0, h1, l0, l1);
}

// exclusive scan, stage 1: 256-element chunks
__global__ void k_scan_local(int n) {
    __shared__ int s[256];
    int tid = threadIdx.x;
    int gid = blockIdx.x * 256 + tid;
    int v = (gid < n) ? g_cnt[gid] : 0;
    s[tid] = v;
    #pragma unroll
    for (int off = 1; off < 256; off <<= 1) {
        __syncthreads();
        int t = (tid >= off) ? s[tid - off] : 0;
        __syncthreads();
        s[tid] += t;
    }
    __syncthreads();
    if (gid < n) g_excl[gid] = s[tid] - v;
    if (tid == 255) g_bsum[blockIdx.x] = s[255];
}

// stage 2 (fused): each block reduces bsum[0..bid) inline; init rowptr/fill/dis
__global__ void k_scan_add(int n) {
    __shared__ int red[256];
    int tid = threadIdx.x;
    int bid = blockIdx.x;
    int s = 0;
    for (int j = tid; j < bid; j += 256) s += g_bsum[j];
    red[tid] = s;
    __syncthreads();
    #pragma unroll
    for (int off = 128; off > 0; off >>= 1) {
        if (tid < off) red[tid] += red[tid + off];
        __syncthreads();
    }
    int base = red[0];
    int i = bid * 256 + tid;
    if (i < n) {
        int v = g_excl[i] + base;
        g_rowptr[i] = v;
        g_fill[i]   = v;
        g_dis[i]    = rsqrtf(g_deg[i] + 1.0f);   // +1 = self-loop weight
    }
}

// scatter edges into CSR; precompute nrm = dis[src]*w*dis[dst]
__global__ void k_fill(const int* __restrict__ ei,
                       const float* __restrict__ ew, int E) {
    int e = blockIdx.x * blockDim.x + threadIdx.x;
    if (e >= E) return;
    int r = ei[e];
    int c = ei[E + e];
    float nrm = g_dis[r] * ew[e] * g_dis[c];
    int pos = atomicAdd(&g_fill[c], 1);
    g_edge[pos] = make_float2(__int_as_float(r), nrm);
}

// ---------------------------------------------------------------------------
// GEMM1 (tensor): g_h1[N,64] = x[N,256] @ W1[256,64] via 3xTF32 mma.sync.
// 256 thr = 8 warps; tile 128 rows x 64 cols; warp w -> rows w*16..+15.
// A fp32 in smem (pad 36, conflict-free); B fragments staged per k-chunk from
// g_wpack into smem and read as ONE LDS.128 per nb (lane-consecutive float4 ->
// conflict-free). Inner loop per k8-step: 4 LDS.32 + 12 cvt + 8 LDS.128 + 12 mma.
// Smem: 18 KB + 16 KB = 34 KB.
// ---------------------------------------------------------------------------
#define G1_ROWS 128

__global__ void k_gemm1(const float* __restrict__ x) {
    __shared__ float  xs[G1_ROWS][36];   // 18 KB, row-major, pad 36
    __shared__ float4 wf[1024];          // 16 KB, frag-order W chunk

    int t    = threadIdx.x;
    int lane = t & 31;
    int w    = t >> 5;            // warp 0..7
    int g    = lane >> 2;         // group 0..7
    int tg   = lane & 3;          // 0..3
    int row0 = blockIdx.x * G1_ROWS;
    int rb   = w * 16;

    float c[8][4];
    #pragma unroll
    for (int nb = 0; nb < 8; nb++)
        #pragma unroll
        for (int i = 0; i < 4; i++) c[nb][i] = 0.0f;

    for (int kc = 0; kc < 8; kc++) {            // k-chunks of 32
        // stage x tile: 128 rows x 32 k = 1024 float4, direct row-major
        #pragma unroll
        for (int j = 0; j < 4; j++) {
            int idx = t + j * 256;
            int r   = idx >> 3;
            int f4  = idx & 7;
            int gr  = row0 + r;
            if (gr >= N_NODES) gr = N_NODES - 1;   // clamped (result discarded)
            float4 v = *(const float4*)(x + (size_t)gr * F_IN + kc * 32 + f4 * 4);
            *(float4*)&xs[r][f4 * 4] = v;
        }
        // stage W frag chunk: 1024 float4
        const float4* wp = g_wpack + kc * 1024;
        #pragma unroll
        for (int j = 0; j < 4; j++)
            wf[t + j * 256] = wp[t + j * 256];
        __syncthreads();

        #pragma unroll
        for (int ks = 0; ks < 4; ks++) {        // 4 k8-steps per chunk
            int k0 = ks * 8;
            float a0 = xs[rb + g][k0 + tg];
            float a1 = xs[rb + g + 8][k0 + tg];
            float a2 = xs[rb + g][k0 + tg + 4];
            float a3 = xs[rb + g + 8][k0 + tg + 4];
            unsigned ahi[4], alo[4];
            ahi[0] = to_tf32(a0); alo[0] = to_tf32(a0 - __uint_as_float(ahi[0]));
            ahi[1] = to_tf32(a1); alo[1] = to_tf32(a1 - __uint_as_float(ahi[1]));
            ahi[2] = to_tf32(a2); alo[2] = to_tf32(a2 - __uint_as_float(ahi[2]));
            ahi[3] = to_tf32(a3); alo[3] = to_tf32(a3 - __uint_as_float(ahi[3]));

            #pragma unroll
            for (int nb = 0; nb < 8; nb++) {
                float4 bv = wf[(ks * 8 + nb) * 32 + lane];
                unsigned bh[2] = {__float_as_uint(bv.x), __float_as_uint(bv.y)};
                unsigned bl[2] = {__float_as_uint(bv.z), __float_as_uint(bv.w)};
                mma_tf32(c[nb], ahi, bh);
                mma_tf32(c[nb], alo, bh);
                mma_tf32(c[nb], ahi, bl);
            }
        }
        __syncthreads();
    }

    int gr0 = row0 + rb + g;
    int gr1 = gr0 + 8;
    #pragma unroll
    for (int nb = 0; nb < 8; nb++) {
        int col = nb * 8 + 2 * tg;
        if (gr0 < N_NODES)
            *(float2*)(g_h1 + (size_t)gr0 * F_HID + col) =
                make_float2(c[nb][0], c[nb][1]);
        if (gr1 < N_NODES)
            *(float2*)(g_h1 + (size_t)gr1 * F_HID + col) =
                make_float2(c[nb][2], c[nb][3]);
    }
}

// ---------------------------------------------------------------------------
// Layer-1 CSR aggregation: 16 threads per node, gather-only, no atomics.
// Fuses self-loop + bias + relu.
// ---------------------------------------------------------------------------
__global__ void k_agg1_csr(const float* __restrict__ b1) {
    int idx  = blockIdx.x * blockDim.x + threadIdx.x;
    int node = idx >> 4;
    int c    = idx & 15;
    if (node >= N_NODES) return;
    int beg = g_rowptr[node];
    int cnt = g_cnt[node];
    float di = g_dis[node];

    float4 acc = make_float4(0.f, 0.f, 0.f, 0.f);
    int j = 0;
    for (; j + 1 < cnt; j += 2) {
        float2 e0 = g_edge[beg + j];
        float2 e1 = g_edge[beg + j + 1];
        int s0 = __float_as_int(e0.x);
        int s1 = __float_as_int(e1.x);
        float4 v0 = *(const float4*)(g_h1 + (size_t)s0 * F_HID + c * 4);
        float4 v1 = *(const float4*)(g_h1 + (size_t)s1 * F_HID + c * 4);
        acc.x += e0.y * v0.x + e1.y * v1.x;
        acc.y += e0.y * v0.y + e1.y * v1.y;
        acc.z += e0.y * v0.z + e1.y * v1.z;
        acc.w += e0.y * v0.w + e1.y * v1.w;
    }
    if (j < cnt) {
        float2 e0 = g_edge[beg + j];
        int s0 = __float_as_int(e0.x);
        float4 v0 = *(const float4*)(g_h1 + (size_t)s0 * F_HID + c * 4);
        acc.x += e0.y * v0.x;
        acc.y += e0.y * v0.y;
        acc.z += e0.y * v0.z;
        acc.w += e0.y * v0.w;
    }

    float s2 = di * di;
    float4 h = *(const float4*)(g_h1 + (size_t)node * F_HID + c * 4);
    float4 b = ((const float4*)b1)[c];
    float4 o;
    o.x = fmaxf(acc.x + s2 * h.x + b.x, 0.0f);
    o.y = fmaxf(acc.y + s2 * h.y + b.y, 0.0f);
    o.z = fmaxf(acc.z + s2 * h.z + b.z, 0.0f);
    o.w = fmaxf(acc.w + s2 * h.w + b.w, 0.0f);
    *(float4*)(g_agg1 + (size_t)node * F_HID + c * 4) = o;
}

// ---------------------------------------------------------------------------
// GEMM2: g_h2[N,40] = g_agg1[N,64] @ W2[64,40]   (FFMA2, R6 config)
// ---------------------------------------------------------------------------
#define G2_ROWS 128

__global__ void k_gemm2(const float* __restrict__ W2) {
    __shared__ float rs[F_HID][G2_ROWS];   // 32 KB, k-major
    __shared__ float ws2[F_HID][F_OUT];    // 10 KB

    int t    = threadIdx.x;
    int row0 = blockIdx.x * G2_ROWS;
    int tx   = t & 7;         // cols tx*5 .. +4
    int ty   = t >> 3;        // rows ty*4 .. +3

    #pragma unroll
    for (int j = 0; j < 3; j++) {
        int i = t + j * 256;
        if (i < 640) ((float4*)ws2)[i] = ((const float4*)W2)[i];
    }
    #pragma unroll
    for (int j = 0; j < 8; j++) {
        int idx = t + j * 256;
        int r   = idx & 127;
        int kq  = idx >> 7;
        int gr  = row0 + r;
        if (gr >= N_NODES) gr = N_NODES - 1;
        float4 v = *(const float4*)(g_agg1 + (size_t)gr * F_HID + kq * 4);
        rs[kq * 4 + 0][r] = v.x;
        rs[kq * 4 + 1][r] = v.y;
        rs[kq * 4 + 2][r] = v.z;
        rs[kq * 4 + 3][r] = v.w;
    }
    __syncthreads();

    unsigned long long acc2[2][5];
    #pragma unroll
    for (int p = 0; p < 2; p++)
        #pragma unroll
        for (int j = 0; j < 5; j++) acc2[p][j] = f2pack(0.0f, 0.0f);

    #pragma unroll
    for (int kk = 0; kk < F_HID; kk++) {
        unsigned long long ap0, ap1;
        lds_v2u64(ap0, ap1, &rs[kk][ty * 4]);
        const float* wrow = &ws2[kk][tx * 5];
        #pragma unroll
        for (int j = 0; j < 5; j++) {
            float bj = wrow[j];
            unsigned long long bd = f2pack(bj, bj);
            fma2(acc2[0][j], ap0, bd);
            fma2(acc2[1][j], ap1, bd);
        }
    }

    #pragma unroll
    for (int p = 0; p < 2; p++) {
        float lo[5], hi[5];
        #pragma unroll
        for (int j = 0; j < 5; j++) f2unpack(acc2[p][j], lo[j], hi[j]);
        int gr0 = row0 + ty * 4 + 2 * p;
        if (gr0 < N_NODES) {
            float* o = g_h2 + (size_t)gr0 * F_OUT + tx * 5;
            #pragma unroll
            for (int j = 0; j < 5; j++) o[j] = lo[j];
        }
        if (gr0 + 1 < N_NODES) {
            float* o = g_h2 + (size_t)(gr0 + 1) * F_OUT + tx * 5;
            #pragma unroll
            for (int j = 0; j < 5; j++) o[j] = hi[j];
        }
    }
}

// ---------------------------------------------------------------------------
// Layer-2 CSR aggregation: 10 threads/node (all active), fuses b2 + self-loop.
// ---------------------------------------------------------------------------
__global__ void k_agg2_csr(const float* __restrict__ b2,
                           float* __restrict__ out) {
    int idx  = blockIdx.x * blockDim.x + threadIdx.x;
    int node = idx / 10;
    int c    = idx - node * 10;
    if (node >= N_NODES) return;
    int beg = g_rowptr[node];
    int cnt = g_cnt[node];
    float di = g_dis[node];

    float4 acc = make_float4(0.f, 0.f, 0.f, 0.f);
    int j = 0;
    for (; j + 1 < cnt; j += 2) {
        float2 e0 = g_edge[beg + j];
        float2 e1 = g_edge[beg + j + 1];
        int s0 = __float_as_int(e0.x);
        int s1 = __float_as_int(e1.x);
        float4 v0 = *(const float4*)(g_h2 + (size_t)s0 * F_OUT + c * 4);
        float4 v1 = *(const float4*)(g_h2 + (size_t)s1 * F_OUT + c * 4);
        acc.x += e0.y * v0.x + e1.y * v1.x;
        acc.y += e0.y * v0.y + e1.y * v1.y;
        acc.z += e0.y * v0.z + e1.y * v1.z;
        acc.w += e0.y * v0.w + e1.y * v1.w;
    }
    if (j < cnt) {
        float2 e0 = g_edge[beg + j];
        int s0 = __float_as_int(e0.x);
        float4 v0 = *(const float4*)(g_h2 + (size_t)s0 * F_OUT + c * 4);
        acc.x += e0.y * v0.x;
        acc.y += e0.y * v0.y;
        acc.z += e0.y * v0.z;
        acc.w += e0.y * v0.w;
    }

    float s2 = di * di;
    float4 h = *(const float4*)(g_h2 + (size_t)node * F_OUT + c * 4);
    float4 b = ((const float4*)b2)[c];
    float4 o;
    o.x = acc.x + s2 * h.x + b.x;
    o.y = acc.y + s2 * h.y + b.y;
    o.z = acc.z + s2 * h.z + b.z;
    o.w = acc.w + s2 * h.w + b.w;
    *(float4*)(out + (size_t)node * F_OUT + c * 4) = o;
}

// ---------------------------------------------------------------------------
extern "C" void kernel_launch(void* const* d_in, const int* in_sizes, int n_in,
                              void* d_out, int out_size) {
    const float* x  = (const float*)d_in[0];
    const int*   ei = (const int*)d_in[1];
    const float* ew = (const float*)d_in[2];
    const float* W1 = (const float*)d_in[3];
    const float* b1 = (const float*)d_in[4];
    const float* W2 = (const float*)d_in[5];
    const float* b2 = (const float*)d_in[6];
    float* out = (float*)d_out;

    int N = in_sizes[0] / F_IN;     // 100000
    int E = in_sizes[2];            // 1600000
    int nblk = (N + 255) / 256;     // 391

    // CSR build + normalization + W pack
    k_zero_cd<<<nblk, 256>>>(N);
    k_packW1<<<32, 256>>>(W1);
    k_count<<<(E + 255) / 256, 256>>>(ei, ew, E);
    k_scan_local<<<nblk, 256>>>(N);
    k_scan_add<<<nblk, 256>>>(N);      // fused bsum-reduce + rowptr + dis
    k_fill<<<(E + 255) / 256, 256>>>(ei, ew, E);

    // layer 1
    k_gemm1<<<(N + G1_ROWS - 1) / G1_ROWS, 256>>>(x);
    {
        long long items = (long long)N * 16;
        k_agg1_csr<<<(int)((items + 255) / 256), 256>>>(b1);
    }

    // layer 2
    k_gemm2<<<(N + G2_ROWS - 1) / G2_ROWS, 256>>>(W2);
    {
        long long items = (long long)N * 10;
        k_agg2_csr<<<(int)((items + 255) / 256), 256>>>(b2, out);
    }
}

// round 16
// speedup vs baseline: 1.2157x; 1.1009x over previous
#include <cuda_runtime.h>

#define N_NODES  100000
#define F_IN     256
#define F_HID    64
#define F_OUT    40
#define EDGE_MAX 1700000

// Scratch (static device globals — no allocation allowed)
__device__ float  g_dis[N_NODES];             // rsqrt(weighted deg + 1)
__device__ float  g_deg[N_NODES];             // weighted degree accumulator
__device__ int    g_cnt[N_NODES];             // edges per destination
__device__ int    g_excl[N_NODES];            // local exclusive scan
__device__ int    g_bsum[512];                // per-block totals
__device__ int    g_rowptr[N_NODES];          // CSR row starts
__device__ int    g_fill[N_NODES];            // fill cursors
__device__ float2 g_edge[EDGE_MAX];           // (src as int bits, nrm)
__device__ float2 g_wpack[8192];              // W1 tf32 (hi only) in mma-frag order
__device__ float  g_h1[N_NODES * F_HID];      // x @ W1
__device__ float  g_agg1[N_NODES * F_HID];    // relu(agg + self + b1)
__device__ float  g_h2[N_NODES * F_OUT];      // relu_out @ W2

// ---------------------------------------------------------------------------
// Packed f32x2 helpers (FFMA2 path, used by gemm2)
// ---------------------------------------------------------------------------
__device__ __forceinline__ unsigned long long f2pack(float lo, float hi) {
    unsigned long long r;
    asm("mov.b64 %0, {%1, %2};" : "=l"(r) : "f"(lo), "f"(hi));
    return r;
}
__device__ __forceinline__ void f2unpack(unsigned long long v, float& lo, float& hi) {
    asm("mov.b64 {%0, %1}, %2;" : "=f"(lo), "=f"(hi) : "l"(v));
}
__device__ __forceinline__ void fma2(unsigned long long& d,
                                     unsigned long long a, unsigned long long b) {
    asm("fma.rn.f32x2 %0, %1, %2, %0;" : "+l"(d) : "l"(a), "l"(b));
}
__device__ __forceinline__ void lds_v2u64(unsigned long long& a, unsigned long long& b,
                                          const void* p) {
    unsigned s = (unsigned)__cvta_generic_to_shared(p);
    asm volatile("ld.shared.v2.u64 {%0, %1}, [%2];" : "=l"(a), "=l"(b) : "r"(s));
}

// ---------------------------------------------------------------------------
// tf32 helpers
// ---------------------------------------------------------------------------
__device__ __forceinline__ unsigned to_tf32(float f) {
    unsigned r;
    asm("cvt.rna.tf32.f32 %0, %1;" : "=r"(r) : "f"(f));
    return r;
}
__device__ __forceinline__ void mma_tf32(float c[4], const unsigned a[4],
                                         const unsigned b[2]) {
    asm volatile(
        "mma.sync.aligned.m16n8k8.row.col.f32.tf32.tf32.f32 "
        "{%0,%1,%2,%3}, {%4,%5,%6,%7}, {%8,%9}, {%0,%1,%2,%3};\n"
        : "+f"(c[0]), "+f"(c[1]), "+f"(c[2]), "+f"(c[3])
        : "r"(a[0]), "r"(a[1]), "r"(a[2]), "r"(a[3]), "r"(b[0]), "r"(b[1]));
}

// ---------------------------------------------------------------------------
// CSR build
// ---------------------------------------------------------------------------
__global__ void k_zero_cd(int n) {
    int i = blockIdx.x * blockDim.x + threadIdx.x;
    if (i < n) { g_cnt[i] = 0; g_deg[i] = 0.0f; }
}

__global__ void k_count(const int* __restrict__ ei,
                        const float* __restrict__ ew, int E) {
    int e = blockIdx.x * blockDim.x + threadIdx.x;
    if (e < E) {
        int c = ei[E + e];
        atomicAdd(&g_cnt[c], 1);
        atomicAdd(&g_deg[c], ew[e]);
    }
}

// Pack W1 (tf32-rounded, hi only) into mma-fragment order:
// g_wpack[((kc*4+ks)*8+nb)*32+lane] = (hi(k,n), hi(k+4,n))
// where k = kc*32+ks*8+(lane&3), n = nb*8+(lane>>2).
__global__ void k_packW1(const float* __restrict__ W1) {
    int idx = blockIdx.x * blockDim.x + threadIdx.x;
    if (idx >= 8192) return;
    int lane = idx & 31;
    int nb   = (idx >> 5) & 7;
    int ks   = (idx >> 8) & 3;
    int kc   = idx >> 10;
    int g    = lane >> 2;
    int tg   = lane & 3;
    int k = kc * 32 + ks * 8 + tg;
    int n = nb * 8 + g;
    float h0 = __uint_as_float(to_tf32(W1[k * F_HID + n]));
    float h1 = __uint_as_float(to_tf32(W1[(k + 4) * F_HID + n]));
    g_wpack[idx] = make_float2(h0, h1);
}

// exclusive scan, stage 1: 256-element chunks
__global__ void k_scan_local(int n) {
    __shared__ int s[256];
    int tid = threadIdx.x;
    int gid = blockIdx.x * 256 + tid;
    int v = (gid < n) ? g_cnt[gid] : 0;
    s[tid] = v;
    #pragma unroll
    for (int off = 1; off < 256; off <<= 1) {
        __syncthreads();
        int t = (tid >= off) ? s[tid - off] : 0;
        __syncthreads();
        s[tid] += t;
    }
    __syncthreads();
    if (gid < n) g_excl[gid] = s[tid] - v;
    if (tid == 255) g_bsum[blockIdx.x] = s[255];
}

// stage 2 (fused): each block reduces bsum[0..bid) inline; init rowptr/fill/dis
__global__ void k_scan_add(int n) {
    __shared__ int red[256];
    int tid = threadIdx.x;
    int bid = blockIdx.x;
    int s = 0;
    for (int j = tid; j < bid; j += 256) s += g_bsum[j];
    red[tid] = s;
    __syncthreads();
    #pragma unroll
    for (int off = 128; off > 0; off >>= 1) {
        if (tid < off) red[tid] += red[tid + off];
        __syncthreads();
    }
    int base = red[0];
    int i = bid * 256 + tid;
    if (i < n) {
        int v = g_excl[i] + base;
        g_rowptr[i] = v;
        g_fill[i]   = v;
        g_dis[i]    = rsqrtf(g_deg[i] + 1.0f);   // +1 = self-loop weight
    }
}

// scatter edges into CSR; precompute nrm = dis[src]*w*dis[dst]
__global__ void k_fill(const int* __restrict__ ei,
                       const float* __restrict__ ew, int E) {
    int e = blockIdx.x * blockDim.x + threadIdx.x;
    if (e >= E) return;
    int r = ei[e];
    int c = ei[E + e];
    float nrm = g_dis[r] * ew[e] * g_dis[c];
    int pos = atomicAdd(&g_fill[c], 1);
    g_edge[pos] = make_float2(__int_as_float(r), nrm);
}

// ---------------------------------------------------------------------------
// GEMM1 (tensor): g_h1[N,64] = x[N,256] @ W1[256,64] via single-tf32 mma.sync.
// 256 thr = 8 warps; tile 128 rows x 64 cols; warp w -> rows w*16..+15.
// A fp32 in smem (pad 36, conflict-free), cvt to tf32 per k8-step; B fragments
// staged per k-chunk into smem, one LDS.64 per nb (lane-consecutive float2 ->
// conflict-free). Inner loop per k8-step: 4 LDS.32 + 4 cvt + 8 LDS.64 + 8 mma.
// Smem: 18 KB + 8 KB = 26 KB.
// ---------------------------------------------------------------------------
#define G1_ROWS 128

__global__ void k_gemm1(const float* __restrict__ x) {
    __shared__ float  xs[G1_ROWS][36];   // 18 KB, row-major, pad 36
    __shared__ float2 wf[1024];          // 8 KB, frag-order W chunk (hi only)

    int t    = threadIdx.x;
    int lane = t & 31;
    int w    = t >> 5;            // warp 0..7
    int g    = lane >> 2;         // group 0..7
    int tg   = lane & 3;          // 0..3
    int row0 = blockIdx.x * G1_ROWS;
    int rb   = w * 16;

    float c[8][4];
    #pragma unroll
    for (int nb = 0; nb < 8; nb++)
        #pragma unroll
        for (int i = 0; i < 4; i++) c[nb][i] = 0.0f;

    for (int kc = 0; kc < 8; kc++) {            // k-chunks of 32
        // stage x tile: 128 rows x 32 k = 1024 float4, direct row-major
        #pragma unroll
        for (int j = 0; j < 4; j++) {
            int idx = t + j * 256;
            int r   = idx >> 3;
            int f4  = idx & 7;
            int gr  = row0 + r;
            if (gr >= N_NODES) gr = N_NODES - 1;   // clamped (result discarded)
            float4 v = *(const float4*)(x + (size_t)gr * F_IN + kc * 32 + f4 * 4);
            *(float4*)&xs[r][f4 * 4] = v;
        }
        // stage W frag chunk: 1024 float2 = 512 float4
        const float4* wp = (const float4*)(g_wpack + kc * 1024);
        ((float4*)wf)[t]       = wp[t];
        ((float4*)wf)[t + 256] = wp[t + 256];
        __syncthreads();

        #pragma unroll
        for (int ks = 0; ks < 4; ks++) {        // 4 k8-steps per chunk
            int k0 = ks * 8;
            unsigned a[4];
            a[0] = to_tf32(xs[rb + g][k0 + tg]);
            a[1] = to_tf32(xs[rb + g + 8][k0 + tg]);
            a[2] = to_tf32(xs[rb + g][k0 + tg + 4]);
            a[3] = to_tf32(xs[rb + g + 8][k0 + tg + 4]);

            #pragma unroll
            for (int nb = 0; nb < 8; nb++) {
                float2 bv = wf[(ks * 8 + nb) * 32 + lane];
                unsigned b[2] = {__float_as_uint(bv.x), __float_as_uint(bv.y)};
                mma_tf32(c[nb], a, b);
            }
        }
        __syncthreads();
    }

    int gr0 = row0 + rb + g;
    int gr1 = gr0 + 8;
    #pragma unroll
    for (int nb = 0; nb < 8; nb++) {
        int col = nb * 8 + 2 * tg;
        if (gr0 < N_NODES)
            *(float2*)(g_h1 + (size_t)gr0 * F_HID + col) =
                make_float2(c[nb][0], c[nb][1]);
        if (gr1 < N_NODES)
            *(float2*)(g_h1 + (size_t)gr1 * F_HID + col) =
                make_float2(c[nb][2], c[nb][3]);
    }
}

// ---------------------------------------------------------------------------
// Layer-1 CSR aggregation: 16 threads per node, gather-only, no atomics.
// Fuses self-loop + bias + relu.
// ---------------------------------------------------------------------------
__global__ void k_agg1_csr(const float* __restrict__ b1) {
    int idx  = blockIdx.x * blockDim.x + threadIdx.x;
    int node = idx >> 4;
    int c    = idx & 15;
    if (node >= N_NODES) return;
    int beg = g_rowptr[node];
    int cnt = g_cnt[node];
    float di = g_dis[node];

    float4 acc = make_float4(0.f, 0.f, 0.f, 0.f);
    int j = 0;
    for (; j + 1 < cnt; j += 2) {
        float2 e0 = g_edge[beg + j];
        float2 e1 = g_edge[beg + j + 1];
        int s0 = __float_as_int(e0.x);
        int s1 = __float_as_int(e1.x);
        float4 v0 = *(const float4*)(g_h1 + (size_t)s0 * F_HID + c * 4);
        float4 v1 = *(const float4*)(g_h1 + (size_t)s1 * F_HID + c * 4);
        acc.x += e0.y * v0.x + e1.y * v1.x;
        acc.y += e0.y * v0.y + e1.y * v1.y;
        acc.z += e0.y * v0.z + e1.y * v1.z;
        acc.w += e0.y * v0.w + e1.y * v1.w;
    }
    if (j < cnt) {
        float2 e0 = g_edge[beg + j];
        int s0 = __float_as_int(e0.x);
        float4 v0 = *(const float4*)(g_h1 + (size_t)s0 * F_HID + c * 4);
        acc.x += e0.y * v0.x;
        acc.y += e0.y * v0.y;
        acc.z += e0.y * v0.z;
        acc.w += e0.y * v0.w;
    }

    float s2 = di * di;
    float4 h = *(const float4*)(g_h1 + (size_t)node * F_HID + c * 4);
    float4 b = ((const float4*)b1)[c];
    float4 o;
    o.x = fmaxf(acc.x + s2 * h.x + b.x, 0.0f);
    o.y = fmaxf(acc.y + s2 * h.y + b.y, 0.0f);
    o.z = fmaxf(acc.z + s2 * h.z + b.z, 0.0f);
    o.w = fmaxf(acc.w + s2 * h.w + b.w, 0.0f);
    *(float4*)(g_agg1 + (size_t)node * F_HID + c * 4) = o;
}

// ---------------------------------------------------------------------------
// GEMM2: g_h2[N,40] = g_agg1[N,64] @ W2[64,40]   (FFMA2, R6 config)
// ---------------------------------------------------------------------------
#define G2_ROWS 128

__global__ void k_gemm2(const float* __restrict__ W2) {
    __shared__ float rs[F_HID][G2_ROWS];   // 32 KB, k-major
    __shared__ float ws2[F_HID][F_OUT];    // 10 KB

    int t    = threadIdx.x;
    int row0 = blockIdx.x * G2_ROWS;
    int tx   = t & 7;         // cols tx*5 .. +4
    int ty   = t >> 3;        // rows ty*4 .. +3

    #pragma unroll
    for (int j = 0; j < 3; j++) {
        int i = t + j * 256;
        if (i < 640) ((float4*)ws2)[i] = ((const float4*)W2)[i];
    }
    #pragma unroll
    for (int j = 0; j < 8; j++) {
        int idx = t + j * 256;
        int r   = idx & 127;
        int kq  = idx >> 7;
        int gr  = row0 + r;
        if (gr >= N_NODES) gr = N_NODES - 1;
        float4 v = *(const float4*)(g_agg1 + (size_t)gr * F_HID + kq * 4);
        rs[kq * 4 + 0][r] = v.x;
        rs[kq * 4 + 1][r] = v.y;
        rs[kq * 4 + 2][r] = v.z;
        rs[kq * 4 + 3][r] = v.w;
    }
    __syncthreads();

    unsigned long long acc2[2][5];
    #pragma unroll
    for (int p = 0; p < 2; p++)
        #pragma unroll
        for (int j = 0; j < 5; j++) acc2[p][j] = f2pack(0.0f, 0.0f);

    #pragma unroll
    for (int kk = 0; kk < F_HID; kk++) {
        unsigned long long ap0, ap1;
        lds_v2u64(ap0, ap1, &rs[kk][ty * 4]);
        const float* wrow = &ws2[kk][tx * 5];
        #pragma unroll
        for (int j = 0; j < 5; j++) {
            float bj = wrow[j];
            unsigned long long bd = f2pack(bj, bj);
            fma2(acc2[0][j], ap0, bd);
            fma2(acc2[1][j], ap1, bd);
        }
    }

    #pragma unroll
    for (int p = 0; p < 2; p++) {
        float lo[5], hi[5];
        #pragma unroll
        for (int j = 0; j < 5; j++) f2unpack(acc2[p][j], lo[j], hi[j]);
        int gr0 = row0 + ty * 4 + 2 * p;
        if (gr0 < N_NODES) {
            float* o = g_h2 + (size_t)gr0 * F_OUT + tx * 5;
            #pragma unroll
            for (int j = 0; j < 5; j++) o[j] = lo[j];
        }
        if (gr0 + 1 < N_NODES) {
            float* o = g_h2 + (size_t)(gr0 + 1) * F_OUT + tx * 5;
            #pragma unroll
            for (int j = 0; j < 5; j++) o[j] = hi[j];
        }
    }
}

// ---------------------------------------------------------------------------
// Layer-2 CSR aggregation: 10 threads/node (all active), fuses b2 + self-loop.
// ---------------------------------------------------------------------------
__global__ void k_agg2_csr(const float* __restrict__ b2,
                           float* __restrict__ out) {
    int idx  = blockIdx.x * blockDim.x + threadIdx.x;
    int node = idx / 10;
    int c    = idx - node * 10;
    if (node >= N_NODES) return;
    int beg = g_rowptr[node];
    int cnt = g_cnt[node];
    float di = g_dis[node];

    float4 acc = make_float4(0.f, 0.f, 0.f, 0.f);
    int j = 0;
    for (; j + 1 < cnt; j += 2) {
        float2 e0 = g_edge[beg + j];
        float2 e1 = g_edge[beg + j + 1];
        int s0 = __float_as_int(e0.x);
        int s1 = __float_as_int(e1.x);
        float4 v0 = *(const float4*)(g_h2 + (size_t)s0 * F_OUT + c * 4);
        float4 v1 = *(const float4*)(g_h2 + (size_t)s1 * F_OUT + c * 4);
        acc.x += e0.y * v0.x + e1.y * v1.x;
        acc.y += e0.y * v0.y + e1.y * v1.y;
        acc.z += e0.y * v0.z + e1.y * v1.z;
        acc.w += e0.y * v0.w + e1.y * v1.w;
    }
    if (j < cnt) {
        float2 e0 = g_edge[beg + j];
        int s0 = __float_as_int(e0.x);
        float4 v0 = *(const float4*)(g_h2 + (size_t)s0 * F_OUT + c * 4);
        acc.x += e0.y * v0.x;
        acc.y += e0.y * v0.y;
        acc.z += e0.y * v0.z;
        acc.w += e0.y * v0.w;
    }

    float s2 = di * di;
    float4 h = *(const float4*)(g_h2 + (size_t)node * F_OUT + c * 4);
    float4 b = ((const float4*)b2)[c];
    float4 o;
    o.x = acc.x + s2 * h.x + b.x;
    o.y = acc.y + s2 * h.y + b.y;
    o.z = acc.z + s2 * h.z + b.z;
    o.w = acc.w + s2 * h.w + b.w;
    *(float4*)(out + (size_t)node * F_OUT + c * 4) = o;
}

// ---------------------------------------------------------------------------
extern "C" void kernel_launch(void* const* d_in, const int* in_sizes, int n_in,
                              void* d_out, int out_size) {
    const float* x  = (const float*)d_in[0];
    const int*   ei = (const int*)d_in[1];
    const float* ew = (const float*)d_in[2];
    const float* W1 = (const float*)d_in[3];
    const float* b1 = (const float*)d_in[4];
    const float* W2 = (const float*)d_in[5];
    const float* b2 = (const float*)d_in[6];
    float* out = (float*)d_out;

    int N = in_sizes[0] / F_IN;     // 100000
    int E = in_sizes[2];            // 1600000
    int nblk = (N + 255) / 256;     // 391

    // CSR build + normalization + W pack
    k_zero_cd<<<nblk, 256>>>(N);
    k_packW1<<<32, 256>>>(W1);
    k_count<<<(E + 255) / 256, 256>>>(ei, ew, E);
    k_scan_local<<<nblk, 256>>>(N);
    k_scan_add<<<nblk, 256>>>(N);      // fused bsum-reduce + rowptr + dis
    k_fill<<<(E + 255) / 256, 256>>>(ei, ew, E);

    // layer 1
    k_gemm1<<<(N + G1_ROWS - 1) / G1_ROWS, 256>>>(x);
    {
        long long items = (long long)N * 16;
        k_agg1_csr<<<(int)((items + 255) / 256), 256>>>(b1);
    }

    // layer 2
    k_gemm2<<<(N + G2_ROWS - 1) / G2_ROWS, 256>>>(W2);
    {
        long long items = (long long)N * 10;
        k_agg2_csr<<<(int)((items + 255) / 256), 256>>>(b2, out);
    }
}

// round 17
// speedup vs baseline: 1.3141x; 1.0810x over previous
#include <cuda_runtime.h>

#define N_NODES  100000
#define F_IN     256
#define F_HID    64
#define F_OUT    40
#define EDGE_MAX 1700000

// Scratch (static device globals — no allocation allowed)
__device__ float  g_dis[N_NODES];             // rsqrt(weighted deg + 1)
__device__ float  g_deg[N_NODES];             // weighted degree accumulator
__device__ int    g_cnt[N_NODES];             // edges per destination
__device__ int    g_excl[N_NODES];            // local exclusive scan
__device__ int    g_bsum[512];                // per-block totals
__device__ int    g_rowptr[N_NODES];          // CSR row starts
__device__ int    g_fill[N_NODES];            // fill cursors
__device__ float2 g_edge[EDGE_MAX];           // (src as int bits, nrm)
__device__ float2 g_wpack[8192];              // W1 tf32 (hi) in mma-frag order
__device__ float2 g_w2pack[1280];             // W2 tf32 (hi) in mma-frag order
__device__ float  g_h1[N_NODES * F_HID];      // x @ W1
__device__ float  g_agg1[N_NODES * F_HID];    // relu(agg + self + b1)
__device__ float  g_h2[N_NODES * F_OUT];      // relu_out @ W2

// ---------------------------------------------------------------------------
// tf32 helpers
// ---------------------------------------------------------------------------
__device__ __forceinline__ unsigned to_tf32(float f) {
    unsigned r;
    asm("cvt.rna.tf32.f32 %0, %1;" : "=r"(r) : "f"(f));
    return r;
}
__device__ __forceinline__ void mma_tf32(float c[4], const unsigned a[4],
                                         const unsigned b[2]) {
    asm volatile(
        "mma.sync.aligned.m16n8k8.row.col.f32.tf32.tf32.f32 "
        "{%0,%1,%2,%3}, {%4,%5,%6,%7}, {%8,%9}, {%0,%1,%2,%3};\n"
        : "+f"(c[0]), "+f"(c[1]), "+f"(c[2]), "+f"(c[3])
        : "r"(a[0]), "r"(a[1]), "r"(a[2]), "r"(a[3]), "r"(b[0]), "r"(b[1]));
}

// ---------------------------------------------------------------------------
// CSR build
// ---------------------------------------------------------------------------
__global__ void k_zero_cd(int n) {
    int i = blockIdx.x * blockDim.x + threadIdx.x;
    if (i < n) { g_cnt[i] = 0; g_deg[i] = 0.0f; }
}

__global__ void k_count(const int* __restrict__ ei,
                        const float* __restrict__ ew, int E) {
    int e = blockIdx.x * blockDim.x + threadIdx.x;
    if (e < E) {
        int c = ei[E + e];
        atomicAdd(&g_cnt[c], 1);
        atomicAdd(&g_deg[c], ew[e]);
    }
}

// Pack W1 (tf32-rounded) into mma-fragment order:
// g_wpack[((kc*4+ks)*8+nb)*32+lane] = (hi(k,n), hi(k+4,n))
// where k = kc*32+ks*8+(lane&3), n = nb*8+(lane>>2).
__global__ void k_packW1(const float* __restrict__ W1) {
    int idx = blockIdx.x * blockDim.x + threadIdx.x;
    if (idx >= 8192) return;
    int lane = idx & 31;
    int nb   = (idx >> 5) & 7;
    int ks   = (idx >> 8) & 3;
    int kc   = idx >> 10;
    int g    = lane >> 2;
    int tg   = lane & 3;
    int k = kc * 32 + ks * 8 + tg;
    int n = nb * 8 + g;
    float h0 = __uint_as_float(to_tf32(W1[k * F_HID + n]));
    float h1 = __uint_as_float(to_tf32(W1[(k + 4) * F_HID + n]));
    g_wpack[idx] = make_float2(h0, h1);
}

// Pack W2 similarly: g_w2pack[(ks*5+nb)*32+lane], k = ks*8+tg, n = nb*8+g.
__global__ void k_packW2(const float* __restrict__ W2) {
    int idx = blockIdx.x * blockDim.x + threadIdx.x;
    if (idx >= 1280) return;
    int lane = idx & 31;
    int nb   = (idx >> 5) % 5;
    int ks   = idx / 160;
    int g    = lane >> 2;
    int tg   = lane & 3;
    int k = ks * 8 + tg;
    int n = nb * 8 + g;
    float h0 = __uint_as_float(to_tf32(W2[k * F_OUT + n]));
    float h1 = __uint_as_float(to_tf32(W2[(k + 4) * F_OUT + n]));
    g_w2pack[idx] = make_float2(h0, h1);
}

// exclusive scan, stage 1: 256-element chunks
__global__ void k_scan_local(int n) {
    __shared__ int s[256];
    int tid = threadIdx.x;
    int gid = blockIdx.x * 256 + tid;
    int v = (gid < n) ? g_cnt[gid] : 0;
    s[tid] = v;
    #pragma unroll
    for (int off = 1; off < 256; off <<= 1) {
        __syncthreads();
        int t = (tid >= off) ? s[tid - off] : 0;
        __syncthreads();
        s[tid] += t;
    }
    __syncthreads();
    if (gid < n) g_excl[gid] = s[tid] - v;
    if (tid == 255) g_bsum[blockIdx.x] = s[255];
}

// stage 2 (fused): each block reduces bsum[0..bid) inline; init rowptr/fill/dis
__global__ void k_scan_add(int n) {
    __shared__ int red[256];
    int tid = threadIdx.x;
    int bid = blockIdx.x;
    int s = 0;
    for (int j = tid; j < bid; j += 256) s += g_bsum[j];
    red[tid] = s;
    __syncthreads();
    #pragma unroll
    for (int off = 128; off > 0; off >>= 1) {
        if (tid < off) red[tid] += red[tid + off];
        __syncthreads();
    }
    int base = red[0];
    int i = bid * 256 + tid;
    if (i < n) {
        int v = g_excl[i] + base;
        g_rowptr[i] = v;
        g_fill[i]   = v;
        g_dis[i]    = rsqrtf(g_deg[i] + 1.0f);   // +1 = self-loop weight
    }
}

// scatter edges into CSR; precompute nrm = dis[src]*w*dis[dst]
__global__ void k_fill(const int* __restrict__ ei,
                       const float* __restrict__ ew, int E) {
    int e = blockIdx.x * blockDim.x + threadIdx.x;
    if (e >= E) return;
    int r = ei[e];
    int c = ei[E + e];
    float nrm = g_dis[r] * ew[e] * g_dis[c];
    int pos = atomicAdd(&g_fill[c], 1);
    g_edge[pos] = make_float2(__int_as_float(r), nrm);
}

// ---------------------------------------------------------------------------
// GEMM1 (tensor): g_h1[N,64] = x[N,256] @ W1[256,64] via single-tf32 mma.sync.
// 256 thr = 8 warps; tile 128 rows x 64 cols; warp w -> rows w*16..+15.
// A fp32 in smem (pad 36, conflict-free); B fragments staged per k-chunk into
// smem, one LDS.64 per nb. Inner: 4 LDS.32 + 4 cvt + 8 LDS.64 + 8 mma / k8.
// ---------------------------------------------------------------------------
#define G1_ROWS 128

__global__ void k_gemm1(const float* __restrict__ x) {
    __shared__ float  xs[G1_ROWS][36];   // 18 KB
    __shared__ float2 wf[1024];          // 8 KB

    int t    = threadIdx.x;
    int lane = t & 31;
    int w    = t >> 5;
    int g    = lane >> 2;
    int tg   = lane & 3;
    int row0 = blockIdx.x * G1_ROWS;
    int rb   = w * 16;

    float c[8][4];
    #pragma unroll
    for (int nb = 0; nb < 8; nb++)
        #pragma unroll
        for (int i = 0; i < 4; i++) c[nb][i] = 0.0f;

    for (int kc = 0; kc < 8; kc++) {
        #pragma unroll
        for (int j = 0; j < 4; j++) {
            int idx = t + j * 256;
            int r   = idx >> 3;
            int f4  = idx & 7;
            int gr  = row0 + r;
            if (gr >= N_NODES) gr = N_NODES - 1;
            float4 v = *(const float4*)(x + (size_t)gr * F_IN + kc * 32 + f4 * 4);
            *(float4*)&xs[r][f4 * 4] = v;
        }
        const float4* wp = (const float4*)(g_wpack + kc * 1024);
        ((float4*)wf)[t]       = wp[t];
        ((float4*)wf)[t + 256] = wp[t + 256];
        __syncthreads();

        #pragma unroll
        for (int ks = 0; ks < 4; ks++) {
            int k0 = ks * 8;
            unsigned a[4];
            a[0] = to_tf32(xs[rb + g][k0 + tg]);
            a[1] = to_tf32(xs[rb + g + 8][k0 + tg]);
            a[2] = to_tf32(xs[rb + g][k0 + tg + 4]);
            a[3] = to_tf32(xs[rb + g + 8][k0 + tg + 4]);
            #pragma unroll
            for (int nb = 0; nb < 8; nb++) {
                float2 bv = wf[(ks * 8 + nb) * 32 + lane];
                unsigned b[2] = {__float_as_uint(bv.x), __float_as_uint(bv.y)};
                mma_tf32(c[nb], a, b);
            }
        }
        __syncthreads();
    }

    int gr0 = row0 + rb + g;
    int gr1 = gr0 + 8;
    #pragma unroll
    for (int nb = 0; nb < 8; nb++) {
        int col = nb * 8 + 2 * tg;
        if (gr0 < N_NODES)
            *(float2*)(g_h1 + (size_t)gr0 * F_HID + col) =
                make_float2(c[nb][0], c[nb][1]);
        if (gr1 < N_NODES)
            *(float2*)(g_h1 + (size_t)gr1 * F_HID + col) =
                make_float2(c[nb][2], c[nb][3]);
    }
}

// ---------------------------------------------------------------------------
// Layer-1 CSR aggregation: 16 threads per node, gather-only, no atomics.
// Fuses self-loop + bias + relu.
// ---------------------------------------------------------------------------
__global__ void k_agg1_csr(const float* __restrict__ b1) {
    int idx  = blockIdx.x * blockDim.x + threadIdx.x;
    int node = idx >> 4;
    int c    = idx & 15;
    if (node >= N_NODES) return;
    int beg = g_rowptr[node];
    int cnt = g_cnt[node];
    float di = g_dis[node];

    float4 acc = make_float4(0.f, 0.f, 0.f, 0.f);
    int j = 0;
    for (; j + 1 < cnt; j += 2) {
        float2 e0 = g_edge[beg + j];
        float2 e1 = g_edge[beg + j + 1];
        int s0 = __float_as_int(e0.x);
        int s1 = __float_as_int(e1.x);
        float4 v0 = *(const float4*)(g_h1 + (size_t)s0 * F_HID + c * 4);
        float4 v1 = *(const float4*)(g_h1 + (size_t)s1 * F_HID + c * 4);
        acc.x += e0.y * v0.x + e1.y * v1.x;
        acc.y += e0.y * v0.y + e1.y * v1.y;
        acc.z += e0.y * v0.z + e1.y * v1.z;
        acc.w += e0.y * v0.w + e1.y * v1.w;
    }
    if (j < cnt) {
        float2 e0 = g_edge[beg + j];
        int s0 = __float_as_int(e0.x);
        float4 v0 = *(const float4*)(g_h1 + (size_t)s0 * F_HID + c * 4);
        acc.x += e0.y * v0.x;
        acc.y += e0.y * v0.y;
        acc.z += e0.y * v0.z;
        acc.w += e0.y * v0.w;
    }

    float s2 = di * di;
    float4 h = *(const float4*)(g_h1 + (size_t)node * F_HID + c * 4);
    float4 b = ((const float4*)b1)[c];
    float4 o;
    o.x = fmaxf(acc.x + s2 * h.x + b.x, 0.0f);
    o.y = fmaxf(acc.y + s2 * h.y + b.y, 0.0f);
    o.z = fmaxf(acc.z + s2 * h.z + b.z, 0.0f);
    o.w = fmaxf(acc.w + s2 * h.w + b.w, 0.0f);
    *(float4*)(g_agg1 + (size_t)node * F_HID + c * 4) = o;
}

// ---------------------------------------------------------------------------
// GEMM2 (tensor): g_h2[N,40] = g_agg1[N,64] @ W2[64,40] via single-tf32 mma.
// 256 thr = 8 warps; tile 128 rows x 40 cols; K=64 in one stage.
// A pad 68 (bank = 4g+tg+const -> conflict-free); W frags: one LDS.64 per nb.
// Smem: 128*68*4 = 34.8 KB + 10 KB = ~45 KB.
// ---------------------------------------------------------------------------
#define G2_ROWS 128

__global__ void k_gemm2(int dummy) {
    __shared__ float  xs[G2_ROWS][68];   // 34.8 KB
    __shared__ float2 wf[1280];          // 10 KB

    int t    = threadIdx.x;
    int lane = t & 31;
    int w    = t >> 5;
    int g    = lane >> 2;
    int tg   = lane & 3;
    int row0 = blockIdx.x * G2_ROWS;
    int rb   = w * 16;

    // stage A: 128 rows x 64 k = 2048 float4
    #pragma unroll
    for (int j = 0; j < 8; j++) {
        int idx = t + j * 256;
        int r   = idx >> 4;
        int f4  = idx & 15;
        int gr  = row0 + r;
        if (gr >= N_NODES) gr = N_NODES - 1;
        float4 v = *(const float4*)(g_agg1 + (size_t)gr * F_HID + f4 * 4);
        *(float4*)&xs[r][f4 * 4] = v;
    }
    // stage W frags: 1280 float2 = 640 float4
    #pragma unroll
    for (int j = 0; j < 3; j++) {
        int i = t + j * 256;
        if (i < 640) ((float4*)wf)[i] = ((const float4*)g_w2pack)[i];
    }
    __syncthreads();

    float c[5][4];
    #pragma unroll
    for (int nb = 0; nb < 5; nb++)
        #pragma unroll
        for (int i = 0; i < 4; i++) c[nb][i] = 0.0f;

    #pragma unroll
    for (int ks = 0; ks < 8; ks++) {
        int k0 = ks * 8;
        unsigned a[4];
        a[0] = to_tf32(xs[rb + g][k0 + tg]);
        a[1] = to_tf32(xs[rb + g + 8][k0 + tg]);
        a[2] = to_tf32(xs[rb + g][k0 + tg + 4]);
        a[3] = to_tf32(xs[rb + g + 8][k0 + tg + 4]);
        #pragma unroll
        for (int nb = 0; nb < 5; nb++) {
            float2 bv = wf[(ks * 5 + nb) * 32 + lane];
            unsigned b[2] = {__float_as_uint(bv.x), __float_as_uint(bv.y)};
            mma_tf32(c[nb], a, b);
        }
    }

    int gr0 = row0 + rb + g;
    int gr1 = gr0 + 8;
    #pragma unroll
    for (int nb = 0; nb < 5; nb++) {
        int col = nb * 8 + 2 * tg;
        if (gr0 < N_NODES)
            *(float2*)(g_h2 + (size_t)gr0 * F_OUT + col) =
                make_float2(c[nb][0], c[nb][1]);
        if (gr1 < N_NODES)
            *(float2*)(g_h2 + (size_t)gr1 * F_OUT + col) =
                make_float2(c[nb][2], c[nb][3]);
    }
}

// ---------------------------------------------------------------------------
// Layer-2 CSR aggregation: 10 threads/node (all active), fuses b2 + self-loop.
// ---------------------------------------------------------------------------
__global__ void k_agg2_csr(const float* __restrict__ b2,
                           float* __restrict__ out) {
    int idx  = blockIdx.x * blockDim.x + threadIdx.x;
    int node = idx / 10;
    int c    = idx - node * 10;
    if (node >= N_NODES) return;
    int beg = g_rowptr[node];
    int cnt = g_cnt[node];
    float di = g_dis[node];

    float4 acc = make_float4(0.f, 0.f, 0.f, 0.f);
    int j = 0;
    for (; j + 1 < cnt; j += 2) {
        float2 e0 = g_edge[beg + j];
        float2 e1 = g_edge[beg + j + 1];
        int s0 = __float_as_int(e0.x);
        int s1 = __float_as_int(e1.x);
        float4 v0 = *(const float4*)(g_h2 + (size_t)s0 * F_OUT + c * 4);
        float4 v1 = *(const float4*)(g_h2 + (size_t)s1 * F_OUT + c * 4);
        acc.x += e0.y * v0.x + e1.y * v1.x;
        acc.y += e0.y * v0.y + e1.y * v1.y;
        acc.z += e0.y * v0.z + e1.y * v1.z;
        acc.w += e0.y * v0.w + e1.y * v1.w;
    }
    if (j < cnt) {
        float2 e0 = g_edge[beg + j];
        int s0 = __float_as_int(e0.x);
        float4 v0 = *(const float4*)(g_h2 + (size_t)s0 * F_OUT + c * 4);
        acc.x += e0.y * v0.x;
        acc.y += e0.y * v0.y;
        acc.z += e0.y * v0.z;
        acc.w += e0.y * v0.w;
    }

    float s2 = di * di;
    float4 h = *(const float4*)(g_h2 + (size_t)node * F_OUT + c * 4);
    float4 b = ((const float4*)b2)[c];
    float4 o;
    o.x = acc.x + s2 * h.x + b.x;
    o.y = acc.y + s2 * h.y + b.y;
    o.z = acc.z + s2 * h.z + b.z;
    o.w = acc.w + s2 * h.w + b.w;
    *(float4*)(out + (size_t)node * F_OUT + c * 4) = o;
}

// ---------------------------------------------------------------------------
extern "C" void kernel_launch(void* const* d_in, const int* in_sizes, int n_in,
                              void* d_out, int out_size) {
    const float* x  = (const float*)d_in[0];
    const int*   ei = (const int*)d_in[1];
    const float* ew = (const float*)d_in[2];
    const float* W1 = (const float*)d_in[3];
    const float* b1 = (const float*)d_in[4];
    const float* W2 = (const float*)d_in[5];
    const float* b2 = (const float*)d_in[6];
    float* out = (float*)d_out;

    int N = in_sizes[0] / F_IN;     // 100000
    int E = in_sizes[2];            // 1600000
    int nblk = (N + 255) / 256;     // 391

    // CSR build + normalization + W packs
    k_zero_cd<<<nblk, 256>>>(N);
    k_packW1<<<32, 256>>>(W1);
    k_packW2<<<5, 256>>>(W2);
    k_count<<<(E + 255) / 256, 256>>>(ei, ew, E);
    k_scan_local<<<nblk, 256>>>(N);
    k_scan_add<<<nblk, 256>>>(N);      // fused bsum-reduce + rowptr + dis
    k_fill<<<(E + 255) / 256, 256>>>(ei, ew, E);

    // layer 1
    k_gemm1<<<(N + G1_ROWS - 1) / G1_ROWS, 256>>>(x);
    {
        long long items = (long long)N * 16;
        k_agg1_csr<<<(int)((items + 255) / 256), 256>>>(b1);
    }

    // layer 2
    k_gemm2<<<(N + G2_ROWS - 1) / G2_ROWS, 256>>>(0);
    {
        long long items = (long long)N * 10;
        k_agg2_csr<<<(int)((items + 255) / 256), 256>>>(b2, out);
    }
}